// round 2
// baseline (speedup 1.0000x reference)
#include <cuda_runtime.h>
#include <cuda_bf16.h>

// Problem constants
#define B_  16
#define R_  64
#define S_  128
#define M_  64
#define L_  128
#define E_  4032            // R*R - R

// Output layout (float elements), 5 concatenated outputs:
#define OFF_INC_ADD  0ull
#define OFF_INC_GAIN 131072ull                       // B*R*L
#define OFF_MEAN     262144ull                       // + B*R*L
#define OFF_LOG      4456448ull                      // + B*R*R*M
#define OFF_MSG      8650752ull                      // + B*R*R*M
// total = 12845056

#define SMB 20   // padded row stride for smean[m][b] (16B-aligned rows, 4-way STS conflict only)

// ---------------- packed f32x2 helpers (sm_103a FFMA2 path) ----------------
__device__ __forceinline__ unsigned long long pk2(float lo, float hi) {
    unsigned long long v;
    asm("mov.b64 %0, {%1, %2};" : "=l"(v) : "f"(lo), "f"(hi));
    return v;
}
__device__ __forceinline__ void unpk(unsigned long long v, float& lo, float& hi) {
    asm("mov.b64 {%0, %1}, %2;" : "=f"(lo), "=f"(hi) : "l"(v));
}
__device__ __forceinline__ unsigned long long fma2(unsigned long long a,
                                                   unsigned long long b,
                                                   unsigned long long c) {
    unsigned long long d;
    asm("fma.rn.f32x2 %0, %1, %2, %3;" : "=l"(d) : "l"(a), "l"(b), "l"(c));
    return d;
}
__device__ __forceinline__ void red_add_v4(float* p, float4 v) {
    asm volatile("red.global.add.v4.f32 [%0], {%1, %2, %3, %4};"
                 :: "l"(p), "f"(v.x), "f"(v.y), "f"(v.z), "f"(v.w) : "memory");
}

// ---------------- init: zero inc regions + scat diagonals ----------------
__global__ void init_kernel(float* __restrict__ out) {
    int idx = blockIdx.x * blockDim.x + threadIdx.x;
    // inc_add + inc_gain: 2*B*R*L = 262144 floats
    if (idx < 2 * B_ * R_ * L_) out[idx] = 0.0f;
    // diagonals of 3 scat outputs: 3 * B*R*M = 196608 entries
    if (idx < 3 * B_ * R_ * M_) {
        int o  = idx / (B_ * R_ * M_);
        int r2 = idx % (B_ * R_ * M_);
        int b  = r2 / (R_ * M_);
        int rm = r2 % (R_ * M_);
        int r  = rm / M_;
        int m  = rm % M_;
        unsigned long long base = (o == 0) ? OFF_MEAN : ((o == 1) ? OFF_LOG : OFF_MSG);
        out[base + ((((unsigned long long)b * R_ + r) * R_ + r) * M_ + m)] = 0.0f;
    }
}

// ---------------- main: one block per edge ----------------
__global__ __launch_bounds__(256) void edge_kernel(
    const float* __restrict__ source,
    const float* __restrict__ mean_w,
    const float* __restrict__ mean_b,
    const float* __restrict__ logstd_w,
    const float* __restrict__ logstd_b,
    const float* __restrict__ add_w,
    const float* __restrict__ gain_w,
    float* __restrict__ out)
{
    const int e = blockIdx.x;
    const int s_idx = e / (R_ - 1);
    const int rem   = e % (R_ - 1);
    const int t_idx = rem + (rem >= s_idx ? 1 : 0);

    __shared__ __align__(16) float xs[S_][B_];      // source transposed [s][b]  (8 KB)
    __shared__ __align__(16) float smean[M_][SMB];  // mean transposed   [m][b]  (5 KB)
    __shared__ __align__(16) float sadd[B_][L_];    // add results       [b][l]  (8 KB)
    __shared__ __align__(16) float sgain[B_][L_];   // gain results      [b][l]  (8 KB)

    const int tid = threadIdx.x;

    // ---- phase 1: stage source rows (coalesced gmem, transposed smem) ----
    for (int i = tid; i < B_ * S_; i += 256) {
        int b = i / S_, s = i % S_;
        xs[s][b] = source[(unsigned long long)b * (R_ * S_) + (unsigned long long)s_idx * S_ + s];
    }
    __syncthreads();

    // ---- phase 2: mean (tid<128) / logstd (tid>=128), each thread: one m, 8 batches ----
    {
        const int  m      = tid & (M_ - 1);
        const int  half   = (tid >> 6) & 1;         // batch half: b0 = half*8
        const bool isMean = (tid < 128);
        const int  b0     = half * 8;

        const float* wrow = (isMean ? mean_w : logstd_w) + ((unsigned long long)e * M_ + m) * S_;
        const float  bias = (isMean ? mean_b : logstd_b)[(unsigned long long)e * M_ + m];
        const float4* wr4 = reinterpret_cast<const float4*>(wrow);

        unsigned long long acc0 = pk2(bias, bias);
        unsigned long long acc1 = acc0, acc2 = acc0, acc3 = acc0;

        #pragma unroll 8
        for (int j = 0; j < S_ / 4; j++) {
            float4 wv = wr4[j];
            unsigned long long w0 = pk2(wv.x, wv.x);
            unsigned long long w1 = pk2(wv.y, wv.y);
            unsigned long long w2 = pk2(wv.z, wv.z);
            unsigned long long w3 = pk2(wv.w, wv.w);
            int s = j * 4;
            {
                ulonglong2 xa = *reinterpret_cast<const ulonglong2*>(&xs[s + 0][b0]);
                acc0 = fma2(xa.x, w0, acc0); acc1 = fma2(xa.y, w0, acc1);
                ulonglong2 xb = *reinterpret_cast<const ulonglong2*>(&xs[s + 0][b0 + 4]);
                acc2 = fma2(xb.x, w0, acc2); acc3 = fma2(xb.y, w0, acc3);
            }
            {
                ulonglong2 xa = *reinterpret_cast<const ulonglong2*>(&xs[s + 1][b0]);
                acc0 = fma2(xa.x, w1, acc0); acc1 = fma2(xa.y, w1, acc1);
                ulonglong2 xb = *reinterpret_cast<const ulonglong2*>(&xs[s + 1][b0 + 4]);
                acc2 = fma2(xb.x, w1, acc2); acc3 = fma2(xb.y, w1, acc3);
            }
            {
                ulonglong2 xa = *reinterpret_cast<const ulonglong2*>(&xs[s + 2][b0]);
                acc0 = fma2(xa.x, w2, acc0); acc1 = fma2(xa.y, w2, acc1);
                ulonglong2 xb = *reinterpret_cast<const ulonglong2*>(&xs[s + 2][b0 + 4]);
                acc2 = fma2(xb.x, w2, acc2); acc3 = fma2(xb.y, w2, acc3);
            }
            {
                ulonglong2 xa = *reinterpret_cast<const ulonglong2*>(&xs[s + 3][b0]);
                acc0 = fma2(xa.x, w3, acc0); acc1 = fma2(xa.y, w3, acc1);
                ulonglong2 xb = *reinterpret_cast<const ulonglong2*>(&xs[s + 3][b0 + 4]);
                acc2 = fma2(xb.x, w3, acc2); acc3 = fma2(xb.y, w3, acc3);
            }
        }

        float v[8];
        unpk(acc0, v[0], v[1]); unpk(acc1, v[2], v[3]);
        unpk(acc2, v[4], v[5]); unpk(acc3, v[6], v[7]);

        const unsigned long long cell = ((unsigned long long)s_idx * R_ + t_idx) * M_ + m;
        if (isMean) {
            #pragma unroll
            for (int i = 0; i < 8; i++) smean[m][b0 + i] = v[i];
            #pragma unroll
            for (int i = 0; i < 8; i++) {
                unsigned long long a = (unsigned long long)(b0 + i) * (R_ * R_ * M_) + cell;
                out[OFF_MEAN + a] = v[i];
                out[OFF_MSG  + a] = v[i];     // msg == mean
            }
        } else {
            #pragma unroll
            for (int i = 0; i < 8; i++) {
                unsigned long long a = (unsigned long long)(b0 + i) * (R_ * R_ * M_) + cell;
                out[OFF_LOG + a] = v[i];
            }
        }
    }
    __syncthreads();

    // ---- phase 3: add (tid<128) / gain (tid>=128), each thread: one l, 16 batches ----
    {
        const int  l     = tid & (L_ - 1);
        const bool isAdd = (tid < 128);

        const float* wrow = (isAdd ? add_w : gain_w) + ((unsigned long long)e * L_ + l) * M_;
        const float4* wr4 = reinterpret_cast<const float4*>(wrow);

        unsigned long long acc[8];
        #pragma unroll
        for (int p = 0; p < 8; p++) acc[p] = 0ull;

        #pragma unroll 4
        for (int j = 0; j < M_ / 4; j++) {
            float4 wv = wr4[j];
            float wk[4] = {wv.x, wv.y, wv.z, wv.w};
            #pragma unroll
            for (int k = 0; k < 4; k++) {
                int m = j * 4 + k;
                unsigned long long wp = pk2(wk[k], wk[k]);
                const ulonglong2* mp = reinterpret_cast<const ulonglong2*>(&smean[m][0]);
                ulonglong2 p0 = mp[0], p1 = mp[1], p2 = mp[2], p3 = mp[3];
                acc[0] = fma2(p0.x, wp, acc[0]); acc[1] = fma2(p0.y, wp, acc[1]);
                acc[2] = fma2(p1.x, wp, acc[2]); acc[3] = fma2(p1.y, wp, acc[3]);
                acc[4] = fma2(p2.x, wp, acc[4]); acc[5] = fma2(p2.y, wp, acc[5]);
                acc[6] = fma2(p3.x, wp, acc[6]); acc[7] = fma2(p3.y, wp, acc[7]);
            }
        }

        float* sres = isAdd ? &sadd[0][0] : &sgain[0][0];
        #pragma unroll
        for (int p = 0; p < 8; p++) {
            float lo, hi;
            unpk(acc[p], lo, hi);
            sres[(2 * p    ) * L_ + l] = lo;
            sres[(2 * p + 1) * L_ + l] = hi;
        }
    }
    __syncthreads();

    // ---- phase 4: vectorized scatter-add into inc_add / inc_gain ----
    // 1024 red.v4 ops: i = (arr:1)(b:4)(q:5)
    for (int i = tid; i < 1024; i += 256) {
        int arr = i >> 9;
        int b   = (i >> 5) & 15;
        int q   = i & 31;
        const float* src = (arr ? &sgain[0][0] : &sadd[0][0]) + b * L_ + q * 4;
        float4 v = *reinterpret_cast<const float4*>(src);
        float* dst = out + (arr ? OFF_INC_GAIN : OFF_INC_ADD)
                   + ((unsigned long long)(b * R_ + t_idx)) * L_ + q * 4;
        red_add_v4(dst, v);
    }
}

extern "C" void kernel_launch(void* const* d_in, const int* in_sizes, int n_in,
                              void* d_out, int out_size) {
    const float* source   = (const float*)d_in[0];
    const float* mean_w   = (const float*)d_in[1];
    const float* mean_b   = (const float*)d_in[2];
    const float* logstd_w = (const float*)d_in[3];
    const float* logstd_b = (const float*)d_in[4];
    const float* add_w    = (const float*)d_in[5];
    const float* gain_w   = (const float*)d_in[6];
    // d_in[7] = src_idx, d_in[8] = tgt_idx (deterministic from e), d_in[9] = deterministic (unused)
    float* out = (float*)d_out;

    init_kernel<<<(2 * B_ * R_ * L_ + 255) / 256, 256>>>(out);
    edge_kernel<<<E_, 256>>>(source, mean_w, mean_b, logstd_w, logstd_b,
                             add_w, gain_w, out);
}

// round 6
// speedup vs baseline: 1.7024x; 1.7024x over previous
#include <cuda_runtime.h>
#include <cuda_bf16.h>

// Problem constants
#define B_  16
#define R_  64
#define S_  128
#define M_  64
#define L_  128
#define E_  4032            // R*R - R

// Output layout (float elements), 5 concatenated outputs:
#define OFF_INC_ADD  0ull
#define OFF_INC_GAIN 131072ull                       // B*R*L
#define OFF_MEAN     262144ull                       // + B*R*L
#define OFF_LOG      4456448ull                      // + B*R*R*M
#define OFF_MSG      8650752ull                      // + B*R*R*M

// Shared layout (floats), total 24576 floats = 96 KB dynamic smem
#define XS_OFF    0            // xs[b][s]        16*128 = 2048
#define WBUF_OFF  2048         // weight union          17408
#define SMEAN_OFF 19456        // smean[b][m]     16*64 = 1024
#define SADD_OFF  20480        // sadd[b][l]     16*128 = 2048
#define SGAIN_OFF 22528        // sgain[b][l]    16*128 = 2048
#define SMEM_FLOATS 24576
// phase-2 weights inside WBUF: stride 132 (128 + 4 pad), mean @0, logstd @8448
#define W2_STRIDE 132
#define W2_LOG    8448
// phase-3 weights inside WBUF: stride 68 (64 + 4 pad), add @0, gain @8704
#define W3_STRIDE 68
#define W3_GAIN   8704

// ---------------- packed f32x2 helpers ----------------
__device__ __forceinline__ unsigned long long fma2(unsigned long long a,
                                                   unsigned long long b,
                                                   unsigned long long c) {
    unsigned long long d;
    asm("fma.rn.f32x2 %0, %1, %2, %3;" : "=l"(d) : "l"(a), "l"(b), "l"(c));
    return d;
}
__device__ __forceinline__ void unpk(unsigned long long v, float& lo, float& hi) {
    asm("mov.b64 {%0, %1}, %2;" : "=f"(lo), "=f"(hi) : "l"(v));
}
__device__ __forceinline__ void red_add_v4(float* p, float4 v) {
    asm volatile("red.global.add.v4.f32 [%0], {%1, %2, %3, %4};"
                 :: "l"(p), "f"(v.x), "f"(v.y), "f"(v.z), "f"(v.w) : "memory");
}
__device__ __forceinline__ void cpa16(float* dst_smem, const float* src) {
    unsigned sa = (unsigned)__cvta_generic_to_shared(dst_smem);
    asm volatile("cp.async.cg.shared.global [%0], [%1], 16;" :: "r"(sa), "l"(src));
}

// ---------------- init: zero inc regions + scat diagonals ----------------
__global__ void init_kernel(float* __restrict__ out) {
    int idx = blockIdx.x * blockDim.x + threadIdx.x;
    if (idx < 2 * B_ * R_ * L_) out[idx] = 0.0f;
    if (idx < 3 * B_ * R_ * M_) {
        int o  = idx / (B_ * R_ * M_);
        int r2 = idx % (B_ * R_ * M_);
        int b  = r2 / (R_ * M_);
        int rm = r2 % (R_ * M_);
        int r  = rm / M_;
        int m  = rm % M_;
        unsigned long long base = (o == 0) ? OFF_MEAN : ((o == 1) ? OFF_LOG : OFF_MSG);
        out[base + ((((unsigned long long)b * R_ + r) * R_ + r) * M_ + m)] = 0.0f;
    }
}

// ---------------- main: one block per edge ----------------
__global__ __launch_bounds__(256) void edge_kernel(
    const float* __restrict__ source,
    const float* __restrict__ mean_w,
    const float* __restrict__ mean_b,
    const float* __restrict__ logstd_w,
    const float* __restrict__ logstd_b,
    const float* __restrict__ add_w,
    const float* __restrict__ gain_w,
    float* __restrict__ out)
{
    extern __shared__ float sm[];
    float* xs    = sm + XS_OFF;      // [b][s]  (b*128 + s)
    float* wbuf  = sm + WBUF_OFF;
    float* smean = sm + SMEAN_OFF;   // [b][m]
    float* sadd  = sm + SADD_OFF;    // [b][l]
    float* sgain = sm + SGAIN_OFF;   // [b][l]

    const int e = blockIdx.x;
    const int s_idx = e / (R_ - 1);
    const int rem   = e % (R_ - 1);
    const int t_idx = rem + (rem >= s_idx ? 1 : 0);
    const int tid = threadIdx.x;

    // ---- staging A: xs (coalesced copy) + mean/logstd weights, all cp.async ----
    {
        // xs: 512 float4 chunks; chunk i: b = i>>5, c = i&31 ; dst = xs + 4*i
        #pragma unroll
        for (int k = 0; k < 2; k++) {
            int i = tid + k * 256;
            int b = i >> 5, c = i & 31;
            cpa16(xs + 4 * i,
                  source + (unsigned long long)b * (R_ * S_) + (unsigned long long)s_idx * S_ + c * 4);
        }
        // weights: 4096 chunks of 16B; c: mat = c/2048, row = (c%2048)/32, col = c%32
        #pragma unroll
        for (int k = 0; k < 16; k++) {
            int c   = tid + k * 256;
            int mat = c >> 11;
            int row = (c & 2047) >> 5;
            int col = c & 31;
            const float* src = (mat ? logstd_w : mean_w)
                             + ((unsigned long long)e * M_ + row) * S_ + col * 4;
            cpa16(wbuf + mat * W2_LOG + row * W2_STRIDE + col * 4, src);
        }
        asm volatile("cp.async.commit_group;");
        asm volatile("cp.async.wait_group 0;");
    }
    __syncthreads();

    // ---- phase 2: mean (k<64) / logstd rows, thread = (row k, batch half) ----
    {
        const int k      = tid & 127;          // row id
        const int half   = tid >> 7;           // 0/1
        const int b0     = half * 8;
        const bool isMean = (k < 64);
        const int m      = isMean ? k : (k - 64);

        const float* wrow = wbuf + (isMean ? m * W2_STRIDE : W2_LOG + m * W2_STRIDE);
        const float  bias = (isMean ? mean_b : logstd_b)[(unsigned long long)e * M_ + m];

        unsigned long long acc[8];
        #pragma unroll
        for (int b = 0; b < 8; b++) acc[b] = 0ull;

        #pragma unroll 4
        for (int j = 0; j < S_ / 8; j++) {          // 8 s per iter (4 s-pairs)
            ulonglong2 wA = *reinterpret_cast<const ulonglong2*>(wrow + j * 8);
            ulonglong2 wB = *reinterpret_cast<const ulonglong2*>(wrow + j * 8 + 4);
            #pragma unroll
            for (int b = 0; b < 8; b++) {
                const float* xr = xs + (b0 + b) * S_ + j * 8;
                ulonglong2 xA = *reinterpret_cast<const ulonglong2*>(xr);
                ulonglong2 xB = *reinterpret_cast<const ulonglong2*>(xr + 4);
                acc[b] = fma2(xA.x, wA.x, acc[b]);
                acc[b] = fma2(xA.y, wA.y, acc[b]);
                acc[b] = fma2(xB.x, wB.x, acc[b]);
                acc[b] = fma2(xB.y, wB.y, acc[b]);
            }
        }

        const unsigned long long cell = ((unsigned long long)s_idx * R_ + t_idx) * M_ + m;
        #pragma unroll
        for (int b = 0; b < 8; b++) {
            float lo, hi;
            unpk(acc[b], lo, hi);
            float v = lo + hi + bias;
            unsigned long long a = (unsigned long long)(b0 + b) * (R_ * R_ * M_) + cell;
            if (isMean) {
                smean[(b0 + b) * M_ + m] = v;
                out[OFF_MEAN + a] = v;
                out[OFF_MSG  + a] = v;       // msg == mean
            } else {
                out[OFF_LOG + a] = v;
            }
        }
    }
    __syncthreads();

    // ---- staging B: add/gain weights into wbuf (overwrites phase-2 weights) ----
    {
        // 4096 chunks of 16B; c: mat = c/2048, row = (c%2048)/16, col = c%16
        #pragma unroll
        for (int k = 0; k < 16; k++) {
            int c   = tid + k * 256;
            int mat = c >> 11;
            int row = (c & 2047) >> 4;
            int col = c & 15;
            const float* src = (mat ? gain_w : add_w)
                             + ((unsigned long long)e * L_ + row) * M_ + col * 4;
            cpa16(wbuf + mat * W3_GAIN + row * W3_STRIDE + col * 4, src);
        }
        asm volatile("cp.async.commit_group;");
        asm volatile("cp.async.wait_group 0;");
    }
    __syncthreads();

    // ---- phase 3: add (tid<128) / gain rows, thread = row l, all 16 batches ----
    {
        const int  l     = tid & 127;
        const bool isAdd = (tid < 128);
        const float* wrow = wbuf + (isAdd ? l * W3_STRIDE : W3_GAIN + l * W3_STRIDE);

        unsigned long long acc[16];
        #pragma unroll
        for (int b = 0; b < 16; b++) acc[b] = 0ull;

        #pragma unroll 2
        for (int j = 0; j < M_ / 8; j++) {          // 8 m per iter
            ulonglong2 wA = *reinterpret_cast<const ulonglong2*>(wrow + j * 8);
            ulonglong2 wB = *reinterpret_cast<const ulonglong2*>(wrow + j * 8 + 4);
            #pragma unroll
            for (int b = 0; b < 16; b++) {
                const float* xr = smean + b * M_ + j * 8;
                ulonglong2 xA = *reinterpret_cast<const ulonglong2*>(xr);
                ulonglong2 xB = *reinterpret_cast<const ulonglong2*>(xr + 4);
                acc[b] = fma2(xA.x, wA.x, acc[b]);
                acc[b] = fma2(xA.y, wA.y, acc[b]);
                acc[b] = fma2(xB.x, wB.x, acc[b]);
                acc[b] = fma2(xB.y, wB.y, acc[b]);
            }
        }

        float* sres = isAdd ? sadd : sgain;
        #pragma unroll
        for (int b = 0; b < 16; b++) {
            float lo, hi;
            unpk(acc[b], lo, hi);
            sres[b * L_ + l] = lo + hi;
        }
    }
    __syncthreads();

    // ---- phase 4: vectorized scatter-add into inc_add / inc_gain ----
    #pragma unroll
    for (int k = 0; k < 4; k++) {
        int i   = tid + k * 256;
        int arr = i >> 9;
        int b   = (i >> 5) & 15;
        int q   = i & 31;
        const float* src = (arr ? sgain : sadd) + b * L_ + q * 4;
        float4 v = *reinterpret_cast<const float4*>(src);
        float* dst = out + (arr ? OFF_INC_GAIN : OFF_INC_ADD)
                   + ((unsigned long long)(b * R_ + t_idx)) * L_ + q * 4;
        red_add_v4(dst, v);
    }
}

extern "C" void kernel_launch(void* const* d_in, const int* in_sizes, int n_in,
                              void* d_out, int out_size) {
    const float* source   = (const float*)d_in[0];
    const float* mean_w   = (const float*)d_in[1];
    const float* mean_b   = (const float*)d_in[2];
    const float* logstd_w = (const float*)d_in[3];
    const float* logstd_b = (const float*)d_in[4];
    const float* add_w    = (const float*)d_in[5];
    const float* gain_w   = (const float*)d_in[6];
    float* out = (float*)d_out;

    static int smem_set = 0;
    // setting an attribute is idempotent & deterministic; do it every call
    cudaFuncSetAttribute(edge_kernel, cudaFuncAttributeMaxDynamicSharedMemorySize,
                         SMEM_FLOATS * 4);
    (void)smem_set;

    init_kernel<<<(2 * B_ * R_ * L_ + 255) / 256, 256>>>(out);
    edge_kernel<<<E_, 256, SMEM_FLOATS * 4>>>(source, mean_w, mean_b,
                                              logstd_w, logstd_b,
                                              add_w, gain_w, out);
}

// round 7
// speedup vs baseline: 1.9388x; 1.1389x over previous
#include <cuda_runtime.h>
#include <cuda_bf16.h>

// Problem constants
#define B_  16
#define R_  64
#define S_  128
#define M_  64
#define L_  128
#define E_  4032            // R*R - R

// Output layout (float elements), 5 concatenated outputs:
#define OFF_INC_ADD  0ull
#define OFF_INC_GAIN 131072ull                       // B*R*L
#define OFF_MEAN     262144ull                       // + B*R*L
#define OFF_LOG      4456448ull                      // + B*R*R*M
#define OFF_MSG      8650752ull                      // + B*R*R*M

// Shared layout (floats), total 24576 floats = 96 KB dynamic smem
#define XS_OFF    0            // xs[b][s]       16*128 = 2048
#define PA_OFF    2048         // SubA weights: 64*132=8448 (mean) / 128*68=8704 (add)
#define QB_OFF    10752        // SubB weights: logstd / gain
#define SMEAN_OFF 19456        // smean[b][m]    16*64 = 1024
#define SADD_OFF  20480        // sadd[b][l]    16*128 = 2048
#define SGAIN_OFF 22528        // sgain[b][l]   16*128 = 2048
#define SMEM_FLOATS 24576
#define W2S 132                // phase-2 weight row stride (128+4)
#define W3S 68                 // phase-3 weight row stride (64+4)

typedef unsigned long long ull;

// ---------------- packed f32x2 helpers ----------------
__device__ __forceinline__ ull fma2(ull a, ull b, ull c) {
    ull d;
    asm("fma.rn.f32x2 %0, %1, %2, %3;" : "=l"(d) : "l"(a), "l"(b), "l"(c));
    return d;
}
__device__ __forceinline__ void unpk(ull v, float& lo, float& hi) {
    asm("mov.b64 {%0, %1}, %2;" : "=f"(lo), "=f"(hi) : "l"(v));
}
__device__ __forceinline__ void red_add_v4(float* p, float4 v) {
    asm volatile("red.global.add.v4.f32 [%0], {%1, %2, %3, %4};"
                 :: "l"(p), "f"(v.x), "f"(v.y), "f"(v.z), "f"(v.w) : "memory");
}
__device__ __forceinline__ void cpa16(float* dst_smem, const float* src) {
    unsigned sa = (unsigned)__cvta_generic_to_shared(dst_smem);
    asm volatile("cp.async.cg.shared.global [%0], [%1], 16;" :: "r"(sa), "l"(src));
}
__device__ __forceinline__ void cp_commit() { asm volatile("cp.async.commit_group;"); }
__device__ __forceinline__ void cp_wait0()  { asm volatile("cp.async.wait_group 0;" ::: "memory"); }
__device__ __forceinline__ void bar_sync(int id, int cnt) {
    asm volatile("bar.sync %0, %1;" :: "r"(id), "r"(cnt) : "memory");
}
__device__ __forceinline__ void bar_arrive(int id, int cnt) {
    asm volatile("bar.arrive %0, %1;" :: "r"(id), "r"(cnt) : "memory");
}

// ---------------- init: zero inc regions + scat diagonals ----------------
__global__ void init_kernel(float* __restrict__ out) {
    int idx = blockIdx.x * blockDim.x + threadIdx.x;
    if (idx < 2 * B_ * R_ * L_) out[idx] = 0.0f;
    if (idx < 3 * B_ * R_ * M_) {
        int o  = idx / (B_ * R_ * M_);
        int r2 = idx % (B_ * R_ * M_);
        int b  = r2 / (R_ * M_);
        int rm = r2 % (R_ * M_);
        int r  = rm / M_;
        int m  = rm % M_;
        ull base = (o == 0) ? OFF_MEAN : ((o == 1) ? OFF_LOG : OFF_MSG);
        out[base + ((((ull)b * R_ + r) * R_ + r) * M_ + m)] = 0.0f;
    }
}

// ---------------- main: one block per edge, two 128-thread sub-pipelines ----
__global__ __launch_bounds__(256, 2) void edge_kernel(
    const float* __restrict__ source,
    const float* __restrict__ mean_w,
    const float* __restrict__ mean_b,
    const float* __restrict__ logstd_w,
    const float* __restrict__ logstd_b,
    const float* __restrict__ add_w,
    const float* __restrict__ gain_w,
    float* __restrict__ out)
{
    extern __shared__ float sm[];
    float* xs    = sm + XS_OFF;      // [b][s]
    float* smean = sm + SMEAN_OFF;   // [b][m]
    float* sadd  = sm + SADD_OFF;    // [b][l]
    float* sgain = sm + SGAIN_OFF;   // [b][l]

    const int e = blockIdx.x;
    const int s_idx = e / (R_ - 1);
    const int rem   = e % (R_ - 1);
    const int t_idx = rem + (rem >= s_idx ? 1 : 0);
    const int tid = threadIdx.x;
    const bool isA = (tid < 128);
    const int  u   = isA ? tid : tid - 128;
    float* WB = sm + (isA ? PA_OFF : QB_OFF);

    // ---- staging 1: xs (all threads) + phase-2 weights (per sub) ----
    #pragma unroll
    for (int k = 0; k < 2; k++) {
        int i = tid + k * 256;
        int b = i >> 5, c = i & 31;
        cpa16(xs + 4 * i,
              source + (ull)b * (R_ * S_) + (ull)s_idx * S_ + c * 4);
    }
    {
        const float* w2src = isA ? mean_w : logstd_w;
        #pragma unroll
        for (int k = 0; k < 16; k++) {
            int c   = u + k * 128;
            int row = c >> 5;
            int col = c & 31;
            cpa16(WB + row * W2S + col * 4,
                  w2src + ((ull)e * M_ + row) * S_ + col * 4);
        }
    }
    cp_commit();
    cp_wait0();
    __syncthreads();

    // ---- phase 2: 2 rows/thread (mg, mg+32), 4 batches/thread ----
    {
        const int warpu = u >> 5;           // 0..3 -> batch quad
        const int mg    = u & 31;
        const int b0    = warpu * 4;

        const float* w0 = WB + mg * W2S;
        const float* w1 = WB + (mg + 32) * W2S;
        const float* bsrc = isA ? mean_b : logstd_b;
        const float bias0 = bsrc[e * M_ + mg];
        const float bias1 = bsrc[e * M_ + mg + 32];

        ull acc[2][4];
        #pragma unroll
        for (int r = 0; r < 2; r++)
            #pragma unroll
            for (int b = 0; b < 4; b++) acc[r][b] = 0ull;

        #pragma unroll 4
        for (int c = 0; c < 16; c++) {      // 8 s per chunk
            const int s0 = c * 8;
            ulonglong2 wa0 = *reinterpret_cast<const ulonglong2*>(w0 + s0);
            ulonglong2 wb0 = *reinterpret_cast<const ulonglong2*>(w0 + s0 + 4);
            ulonglong2 wa1 = *reinterpret_cast<const ulonglong2*>(w1 + s0);
            ulonglong2 wb1 = *reinterpret_cast<const ulonglong2*>(w1 + s0 + 4);
            #pragma unroll
            for (int b = 0; b < 4; b++) {
                const float* xr = xs + (b0 + b) * S_ + s0;
                ulonglong2 xa = *reinterpret_cast<const ulonglong2*>(xr);
                ulonglong2 xb = *reinterpret_cast<const ulonglong2*>(xr + 4);
                acc[0][b] = fma2(xa.x, wa0.x, acc[0][b]);
                acc[0][b] = fma2(xa.y, wa0.y, acc[0][b]);
                acc[0][b] = fma2(xb.x, wb0.x, acc[0][b]);
                acc[0][b] = fma2(xb.y, wb0.y, acc[0][b]);
                acc[1][b] = fma2(xa.x, wa1.x, acc[1][b]);
                acc[1][b] = fma2(xa.y, wa1.y, acc[1][b]);
                acc[1][b] = fma2(xb.x, wb1.x, acc[1][b]);
                acc[1][b] = fma2(xb.y, wb1.y, acc[1][b]);
            }
        }

        const ull cellb = (ull)(s_idx * R_ + t_idx) * M_;
        #pragma unroll
        for (int r = 0; r < 2; r++) {
            const int m = mg + 32 * r;
            const float bias = r ? bias1 : bias0;
            #pragma unroll
            for (int b = 0; b < 4; b++) {
                float lo, hi;
                unpk(acc[r][b], lo, hi);
                float v = lo + hi + bias;
                ull a = (ull)(b0 + b) * (R_ * R_ * M_) + cellb + m;
                if (isA) {
                    smean[(b0 + b) * M_ + m] = v;
                    out[OFF_MEAN + a] = v;
                    out[OFF_MSG  + a] = v;          // msg == mean
                } else {
                    out[OFF_LOG + a] = v;
                }
            }
        }
    }

    // ---- sub barriers: free own weight buffer; publish smean (A -> B) ----
    if (isA) { bar_sync(1, 128); bar_arrive(3, 256); }
    else     { bar_sync(2, 128); }

    // ---- staging 2: phase-3 weights (per sub) ----
    {
        const float* w3src = isA ? add_w : gain_w;
        #pragma unroll
        for (int k = 0; k < 16; k++) {
            int c   = u + k * 128;
            int row = c >> 4;
            int col = c & 15;
            cpa16(WB + row * W3S + col * 4,
                  w3src + ((ull)e * L_ + row) * M_ + col * 4);
        }
    }
    cp_commit();
    cp_wait0();
    if (isA) { bar_sync(1, 128); }
    else     { bar_sync(2, 128); bar_sync(3, 256); }  // wait smean from SubA

    // ---- phase 3: 2 rows/thread (lg, lg+64), 8 batches/thread ----
    {
        const int bs = u >> 6;              // 0/1 -> batch octet
        const int lg = u & 63;
        const int b0 = bs * 8;

        const float* w0 = WB + lg * W3S;
        const float* w1 = WB + (lg + 64) * W3S;

        ull acc[2][8];
        #pragma unroll
        for (int r = 0; r < 2; r++)
            #pragma unroll
            for (int b = 0; b < 8; b++) acc[r][b] = 0ull;

        #pragma unroll 2
        for (int c = 0; c < 8; c++) {       // 8 m per chunk
            const int m0 = c * 8;
            ulonglong2 wa0 = *reinterpret_cast<const ulonglong2*>(w0 + m0);
            ulonglong2 wb0 = *reinterpret_cast<const ulonglong2*>(w0 + m0 + 4);
            ulonglong2 wa1 = *reinterpret_cast<const ulonglong2*>(w1 + m0);
            ulonglong2 wb1 = *reinterpret_cast<const ulonglong2*>(w1 + m0 + 4);
            #pragma unroll
            for (int b = 0; b < 8; b++) {
                const float* mr = smean + (b0 + b) * M_ + m0;
                ulonglong2 xa = *reinterpret_cast<const ulonglong2*>(mr);
                ulonglong2 xb = *reinterpret_cast<const ulonglong2*>(mr + 4);
                acc[0][b] = fma2(xa.x, wa0.x, acc[0][b]);
                acc[0][b] = fma2(xa.y, wa0.y, acc[0][b]);
                acc[0][b] = fma2(xb.x, wb0.x, acc[0][b]);
                acc[0][b] = fma2(xb.y, wb0.y, acc[0][b]);
                acc[1][b] = fma2(xa.x, wa1.x, acc[1][b]);
                acc[1][b] = fma2(xa.y, wa1.y, acc[1][b]);
                acc[1][b] = fma2(xb.x, wb1.x, acc[1][b]);
                acc[1][b] = fma2(xb.y, wb1.y, acc[1][b]);
            }
        }

        float* sres = isA ? sadd : sgain;
        #pragma unroll
        for (int r = 0; r < 2; r++) {
            const int l = lg + 64 * r;
            #pragma unroll
            for (int b = 0; b < 8; b++) {
                float lo, hi;
                unpk(acc[r][b], lo, hi);
                sres[(b0 + b) * L_ + l] = lo + hi;
            }
        }
    }
    if (isA) bar_sync(1, 128);
    else     bar_sync(2, 128);

    // ---- phase 4: vectorized scatter-add (each sub reduces its own array) ----
    {
        float* sres = isA ? sadd : sgain;
        const ull offI = isA ? OFF_INC_ADD : OFF_INC_GAIN;
        #pragma unroll
        for (int k = 0; k < 4; k++) {
            int i = u + k * 128;
            int b = i >> 5;
            int q = i & 31;
            float4 v = *reinterpret_cast<const float4*>(sres + b * L_ + q * 4);
            float* dst = out + offI + (ull)(b * R_ + t_idx) * L_ + q * 4;
            red_add_v4(dst, v);
        }
    }
}

extern "C" void kernel_launch(void* const* d_in, const int* in_sizes, int n_in,
                              void* d_out, int out_size) {
    const float* source   = (const float*)d_in[0];
    const float* mean_w   = (const float*)d_in[1];
    const float* mean_b   = (const float*)d_in[2];
    const float* logstd_w = (const float*)d_in[3];
    const float* logstd_b = (const float*)d_in[4];
    const float* add_w    = (const float*)d_in[5];
    const float* gain_w   = (const float*)d_in[6];
    float* out = (float*)d_out;

    cudaFuncSetAttribute(edge_kernel, cudaFuncAttributeMaxDynamicSharedMemorySize,
                         SMEM_FLOATS * 4);

    init_kernel<<<(2 * B_ * R_ * L_ + 255) / 256, 256>>>(out);
    edge_kernel<<<E_, 256, SMEM_FLOATS * 4>>>(source, mean_w, mean_b,
                                              logstd_w, logstd_b,
                                              add_w, gain_w, out);
}